// round 10
// baseline (speedup 1.0000x reference)
#include <cuda_runtime.h>
#include <cuda_bf16.h>
#include <math.h>
#include <stdint.h>

#define BB 64
#define NN 4096
#define DD 128
#define SS 65536
#define KTOP 16
#define NCH 16                        // filter chunks per b
#define CHSZ (SS / NCH)               // 4096
#define NBLK 512                      // k4f blocks (128 s each)
#define SCAP 2560                     // survivor capacity (worst bound 2048+ties)

typedef unsigned long long ull;

// ---------------- scratch (device globals; allocation-free) ----------------
__device__ float g_qpart[BB * 4 * DD];   // per-CTA partial gelu sums
__device__ float g_qt[DD * BB];          // normalized q^T: [d][b]
__device__ float g_sim[(size_t)BB * SS]; // cosine sims                    (16 MB)
__device__ float g_proto[BB * DD];
__device__ float g_bmax[BB * NBLK];      // per-(b, k4f-block) max
__device__ float g_thr[BB];              // per-b threshold (16th of block maxes)
__device__ int   g_scnt[BB];             // per-b survivor count
__device__ float g_surv_v[BB * SCAP];
__device__ int   g_surv_i[BB * SCAP];

// ---------------- generic helpers ----------------
__device__ __forceinline__ ull ffma2(ull a, ull b, ull c) {
    ull d;
    asm("fma.rn.f32x2 %0, %1, %2, %3;" : "=l"(d) : "l"(a), "l"(b), "l"(c));
    return d;
}
__device__ __forceinline__ ull dup2(float x) {
    ull d;
    asm("mov.b64 %0, {%1, %1};" : "=l"(d) : "f"(x));
    return d;
}
__device__ __forceinline__ void unpack2(ull v, float& lo, float& hi) {
    asm("mov.b64 {%0, %1}, %2;" : "=f"(lo), "=f"(hi) : "l"(v));
}
// fast exact-enough gelu: erf via Abramowitz-Stegun 7.1.26 (|eps|<=1.5e-7)
__device__ __forceinline__ float gelu_exact(float z) {
    float x = z * 0.70710678118654752f;
    float ax = fabsf(x);
    float t = __fdividef(1.0f, fmaf(0.3275911f, ax, 1.0f));
    float p = t * fmaf(t, fmaf(t, fmaf(t, fmaf(t, 1.061405429f, -1.453152027f),
                                       1.421413741f), -0.284496736f), 0.254829592f);
    float e = __expf(-x * x);
    float er = copysignf(fmaf(-p, e, 1.0f), x);
    return 0.5f * z * (1.0f + er);
}
// split fp32 -> bf16 hi + bf16 lo (hi+lo represents v to ~2^-17)
__device__ __forceinline__ void bsplit(float v, uint16_t& h, uint16_t& l) {
    __nv_bfloat16 bh = __float2bfloat16_rn(v);
    float r = v - __bfloat162float(bh);
    __nv_bfloat16 bl = __float2bfloat16_rn(r);
    h = *(uint16_t*)&bh; l = *(uint16_t*)&bl;
}
__device__ __forceinline__ uint32_t bpack(float lo, float hi) {
    uint32_t r;
    asm("cvt.rn.bf16x2.f32 %0, %1, %2;" : "=r"(r) : "f"(hi), "f"(lo));
    return r;
}

// bf16 m16n8k16 mma.sync
__device__ __forceinline__ void mma_bf16(float* c, uint32_t a0, uint32_t a1,
                                         uint32_t a2, uint32_t a3,
                                         uint32_t b0, uint32_t b1) {
    asm volatile(
        "mma.sync.aligned.m16n8k16.row.col.f32.bf16.bf16.f32 "
        "{%0,%1,%2,%3}, {%4,%5,%6,%7}, {%8,%9}, {%0,%1,%2,%3};"
        : "+f"(c[0]), "+f"(c[1]), "+f"(c[2]), "+f"(c[3])
        : "r"(a0), "r"(a1), "r"(a2), "r"(a3), "r"(b0), "r"(b1));
}

// ---------------- K2: bf16 hi/lo-W mma conv1d+GeLU+sum-over-n -----------
// grid 256: cta = (b, quarter). 8 tiles of 128 positions = 16 k-half steps.
// 2-stage A ring, 1 sync/step, 2 CTAs/SM.
#define WS16 136                     // bf16 per W row (128 + 8 pad)
#define AS16 72                      // bf16 per A row (64 + 8 pad)
#define AB16 (128 * AS16)            // 9216 bf16 per A buffer (18432 B)
#define O_W    0                     // Whi: 34816 B
#define O_WLO  34816                 // Wlo: 34816 B
#define O_A    69632                 // 2 * 18432 = 36864 B
#define O_BIAS 106496                // 512 B
#define O_RED  107008                // 1024 B
#define K2_SMEM 108032

__global__ void __launch_bounds__(256, 2) k2_mma(const float* __restrict__ x,
                                                 const float* __restrict__ w,
                                                 const float* __restrict__ bias) {
    extern __shared__ char smc[];
    uint16_t* ws    = (uint16_t*)(smc + O_W);
    uint16_t* wl    = (uint16_t*)(smc + O_WLO);
    uint16_t* ab    = (uint16_t*)(smc + O_A);
    float*    sbias = (float*)(smc + O_BIAS);
    float*    red   = (float*)(smc + O_RED);

    int tid = threadIdx.x, wid = tid >> 5, lane = tid & 31;
    int g = lane >> 2, kc = lane & 3;
    int cta = blockIdx.x, b = cta >> 2, quarter = cta & 3;
    const float* xb = x + ((size_t)b * NN + (size_t)quarter * 1024) * DD;

    // ---- stage W as bf16 hi/lo [e][k] ----
    for (int i = tid; i < 4096; i += 256) {      // float4 over [128e][32]
        float4 v = ((const float4*)w)[i];
        int e = i >> 5, d0 = (i & 31) * 4;
        uint16_t h[4], l[4];
        bsplit(v.x, h[0], l[0]); bsplit(v.y, h[1], l[1]);
        bsplit(v.z, h[2], l[2]); bsplit(v.w, h[3], l[3]);
        *(uint2*)&ws[e * WS16 + d0] = make_uint2((uint32_t)h[0] | ((uint32_t)h[1] << 16),
                                                 (uint32_t)h[2] | ((uint32_t)h[3] << 16));
        *(uint2*)&wl[e * WS16 + d0] = make_uint2((uint32_t)l[0] | ((uint32_t)l[1] << 16),
                                                 (uint32_t)l[2] | ((uint32_t)l[3] << 16));
    }
    if (tid < 128) sbias[tid] = bias[tid];

    int ew = (wid & 3) * 32;

    float c[4][4][4];
    #pragma unroll
    for (int mf = 0; mf < 4; ++mf)
        #pragma unroll
        for (int ef = 0; ef < 4; ++ef)
            #pragma unroll
            for (int q = 0; q < 4; ++q) c[mf][ef][q] = 0.f;
    float es[8];
    #pragma unroll
    for (int s = 0; s < 8; ++s) es[s] = 0.f;

    float4 r8[8];
    auto ldg = [&](int gstep) {
        int t = gstep >> 1, h = gstep & 1;
        const float* base = xb + (size_t)t * (128 * DD) + h * 64;
        #pragma unroll
        for (int j = 0; j < 8; ++j) {
            int idx = j * 256 + tid;             // 0..2047
            int row = idx >> 4, seg = idx & 15;
            r8[j] = *(const float4*)(base + (size_t)row * DD + seg * 4);
        }
    };
    auto sts = [&](int buf) {
        uint16_t* d = ab + buf * AB16;
        #pragma unroll
        for (int j = 0; j < 8; ++j) {
            int idx = j * 256 + tid;
            int row = idx >> 4, seg = idx & 15;
            uint2 p = make_uint2(bpack(r8[j].x, r8[j].y), bpack(r8[j].z, r8[j].w));
            *(uint2*)&d[row * AS16 + seg * 4] = p;
        }
    };

    ldg(0); sts(0);
    ldg(1);
    __syncthreads();                 // W + bias + buf0 visible

    int mrow = (wid >> 2) * 64 + g;

    #pragma unroll 1
    for (int step = 0; step < 16; ++step) {
        if (step < 15) sts((step + 1) & 1);      // regs for step+1 -> ring
        if (step < 14) ldg(step + 2);            // prefetch step+2

        const uint16_t* A = ab + (step & 1) * AB16;
        int kg0 = (step & 1) * 64;               // k offset into W
        #pragma unroll
        for (int ks = 0; ks < 4; ++ks) {
            int kb = ks * 16;
            uint32_t a[4][4];
            #pragma unroll
            for (int mf = 0; mf < 4; ++mf) {
                int r = mrow + mf * 16;
                a[mf][0] = *(const uint32_t*)&A[r * AS16 + kb + 2 * kc];
                a[mf][1] = *(const uint32_t*)&A[(r + 8) * AS16 + kb + 2 * kc];
                a[mf][2] = *(const uint32_t*)&A[r * AS16 + kb + 2 * kc + 8];
                a[mf][3] = *(const uint32_t*)&A[(r + 8) * AS16 + kb + 2 * kc + 8];
            }
            #pragma unroll
            for (int ef = 0; ef < 4; ++ef) {
                int e = ew + ef * 8 + g;
                uint32_t b0 = *(const uint32_t*)&ws[e * WS16 + kg0 + kb + 2 * kc];
                uint32_t b1 = *(const uint32_t*)&ws[e * WS16 + kg0 + kb + 2 * kc + 8];
                uint32_t c0 = *(const uint32_t*)&wl[e * WS16 + kg0 + kb + 2 * kc];
                uint32_t c1 = *(const uint32_t*)&wl[e * WS16 + kg0 + kb + 2 * kc + 8];
                #pragma unroll
                for (int mf = 0; mf < 4; ++mf) {
                    mma_bf16(c[mf][ef], a[mf][0], a[mf][1], a[mf][2], a[mf][3], b0, b1);
                    mma_bf16(c[mf][ef], a[mf][0], a[mf][1], a[mf][2], a[mf][3], c0, c1);
                }
            }
        }

        if ((step & 1) == 1) {                   // tile done: gelu + accumulate
            #pragma unroll
            for (int mf = 0; mf < 4; ++mf)
                #pragma unroll
                for (int ef = 0; ef < 4; ++ef)
                    #pragma unroll
                    for (int q = 0; q < 4; ++q) {
                        int s = ef * 2 + (q & 1);
                        float bv = sbias[ew + ef * 8 + 2 * kc + (q & 1)];
                        es[s] += gelu_exact(c[mf][ef][q] + bv);
                        c[mf][ef][q] = 0.f;
                    }
        }
        __syncthreads();                         // publish sts, guard reuse
    }

    #pragma unroll
    for (int off = 16; off >= 4; off >>= 1)
        #pragma unroll
        for (int s = 0; s < 8; ++s)
            es[s] += __shfl_xor_sync(0xffffffffu, es[s], off);
    if (g == 0) {
        #pragma unroll
        for (int s = 0; s < 8; ++s) {
            int ecol = ew + (s >> 1) * 8 + 2 * kc + (s & 1);
            red[(wid >> 2) * 128 + ecol] = es[s];
        }
    }
    __syncthreads();
    if (tid < 128)
        g_qpart[(b * 4 + quarter) * 128 + tid] = red[tid] + red[128 + tid];
}

// ---------------- K3: finalize q + normalize + transpose ----------------
__global__ void k3_q() {
    int b = blockIdx.x, e = threadIdx.x;
    float q = g_qpart[b * 512 + e] + g_qpart[b * 512 + 128 + e] +
              g_qpart[b * 512 + 256 + e] + g_qpart[b * 512 + 384 + e];
    __shared__ float sr[128];
    sr[e] = q * q;
    __syncthreads();
    for (int off = 64; off; off >>= 1) {
        if (e < off) sr[e] += sr[e + off];
        __syncthreads();
    }
    float inv = 1.0f / fmaxf(sqrtf(sr[0]), 1e-12f);
    g_qt[e * 64 + b] = q * inv;
}

// ---------------- K4f: fused normalize + sim GEMM + block maxes ---------
#define S4_QS  0
#define S4_MT  8192
#define S4_TL  24576
#define S4_INV 32832
#define K4_SMEM ((32832 + 64) * 4)   // 131584 bytes

__global__ void __launch_bounds__(256, 1) k4f(const float* __restrict__ mem) {
    extern __shared__ float s4[];
    float* qs   = s4 + S4_QS;
    float* mt   = s4 + S4_MT;
    float* tile = s4 + S4_TL;
    float* inv  = s4 + S4_INV;
    int tid = threadIdx.x;
    int s0 = blockIdx.x * 128;

    for (int i = tid; i < 8192; i += 256) qs[i] = g_qt[i];

    #pragma unroll 1
    for (int half = 0; half < 2; ++half) {
        int c = tid & 31, r0 = tid >> 5;
        #pragma unroll
        for (int it = 0; it < 8; ++it) {
            int r = r0 + it * 8;
            float4 v = *(const float4*)&mem[(size_t)(s0 + half * 64 + r) * 128 + c * 4];
            tile[r * 129 + c * 4 + 0] = v.x; tile[r * 129 + c * 4 + 1] = v.y;
            tile[r * 129 + c * 4 + 2] = v.z; tile[r * 129 + c * 4 + 3] = v.w;
        }
        __syncthreads();
        if (tid < 64) {
            float acc = 0.f;
            #pragma unroll 8
            for (int k = 0; k < 128; ++k) { float t = tile[tid * 129 + k]; acc = fmaf(t, t, acc); }
            inv[tid] = 1.0f / fmaxf(sqrtf(acc), 1e-12f);
        }
        __syncthreads();
        int r = tid & 63, kg = tid >> 6;
        float iv = inv[r];
        #pragma unroll
        for (int it = 0; it < 32; ++it) {
            int k = kg + it * 4;
            mt[k * 128 + half * 64 + r] = tile[r * 129 + k] * iv;
        }
        __syncthreads();
    }

    int tm = tid >> 4, tn = tid & 15;
    ull acc[4][4];
    #pragma unroll
    for (int i = 0; i < 4; ++i)
        #pragma unroll
        for (int j = 0; j < 4; ++j) acc[i][j] = 0ull;

    #pragma unroll 8
    for (int k = 0; k < 128; ++k) {
        float4 av = *(const float4*)&qs[k * 64 + tm * 4];
        ull a0 = dup2(av.x), a1 = dup2(av.y), a2 = dup2(av.z), a3 = dup2(av.w);
        const float* mrow = mt + k * 128;
        #pragma unroll
        for (int gg = 0; gg < 2; ++gg) {
            ulonglong2 bv = *(const ulonglong2*)(mrow + (tn + gg * 16) * 4);
            acc[0][gg * 2 + 0] = ffma2(a0, bv.x, acc[0][gg * 2 + 0]);
            acc[0][gg * 2 + 1] = ffma2(a0, bv.y, acc[0][gg * 2 + 1]);
            acc[1][gg * 2 + 0] = ffma2(a1, bv.x, acc[1][gg * 2 + 0]);
            acc[1][gg * 2 + 1] = ffma2(a1, bv.y, acc[1][gg * 2 + 1]);
            acc[2][gg * 2 + 0] = ffma2(a2, bv.x, acc[2][gg * 2 + 0]);
            acc[2][gg * 2 + 1] = ffma2(a2, bv.y, acc[2][gg * 2 + 1]);
            acc[3][gg * 2 + 0] = ffma2(a3, bv.x, acc[3][gg * 2 + 0]);
            acc[3][gg * 2 + 1] = ffma2(a3, bv.y, acc[3][gg * 2 + 1]);
        }
    }
    #pragma unroll
    for (int i = 0; i < 4; ++i) {
        int b = tm * 4 + i;
        float4 o0, o1;
        unpack2(acc[i][0], o0.x, o0.y);
        unpack2(acc[i][1], o0.z, o0.w);
        unpack2(acc[i][2], o1.x, o1.y);
        unpack2(acc[i][3], o1.z, o1.w);
        *(float4*)&g_sim[(size_t)b * SS + s0 + tn * 4] = o0;
        *(float4*)&g_sim[(size_t)b * SS + s0 + (tn + 16) * 4] = o1;
        float mx = fmaxf(fmaxf(fmaxf(o0.x, o0.y), fmaxf(o0.z, o0.w)),
                         fmaxf(fmaxf(o1.x, o1.y), fmaxf(o1.z, o1.w)));
        #pragma unroll
        for (int off = 1; off < 16; off <<= 1)
            mx = fmaxf(mx, __shfl_xor_sync(0xffffffffu, mx, off));
        if (tn == 0) g_bmax[b * NBLK + blockIdx.x] = mx;
    }
}

// ---------------- K5t: per-b threshold = 16th largest of block maxes ----
__global__ void __launch_bounds__(128) k5t() {
    __shared__ float sm5[NBLK];
    int b = blockIdx.x, tid = threadIdx.x, lane = tid & 31;
    for (int i = tid; i < NBLK; i += 128) sm5[i] = g_bmax[b * NBLK + i];
    __syncthreads();
    if (tid < 32) {
        float lv[NBLK / 32];
        #pragma unroll
        for (int j = 0; j < NBLK / 32; ++j) lv[j] = sm5[lane * (NBLK / 32) + j];
        float T = 0.f;
        #pragma unroll 1
        for (int r = 0; r < KTOP; ++r) {
            float mv = lv[0]; int lm = 0;
            #pragma unroll
            for (int j = 1; j < NBLK / 32; ++j) if (lv[j] > mv) { mv = lv[j]; lm = j; }
            float bv = mv; int bl = lane;
            #pragma unroll
            for (int off = 16; off; off >>= 1) {
                float ov = __shfl_xor_sync(0xffffffffu, bv, off);
                int ol = __shfl_xor_sync(0xffffffffu, bl, off);
                if (ov > bv || (ov == bv && ol < bl)) { bv = ov; bl = ol; }
            }
            if (lane == bl) {
                #pragma unroll
                for (int j = 0; j < NBLK / 32; ++j) if (j == lm) lv[j] = -1e30f;
            }
            T = bv;
        }
        if (lane == 0) { g_thr[b] = T; g_scnt[b] = 0; }
    }
}

// ---------------- K5s: stream filter (no selection) ---------------------
__global__ void __launch_bounds__(256) k5s() {
    int b = blockIdx.y, ch = blockIdx.x;
    int tid = threadIdx.x;
    float T = g_thr[b];
    const float4* rowv = (const float4*)(g_sim + (size_t)b * SS + (size_t)ch * CHSZ);
    int base = ch * CHSZ;
    #pragma unroll
    for (int it = 0; it < 4; ++it) {
        float4 v = rowv[it * 256 + tid];
        float vm = fmaxf(fmaxf(v.x, v.y), fmaxf(v.z, v.w));
        if (vm >= T) {
            float vals[4] = {v.x, v.y, v.z, v.w};
            int sb = base + (it * 256 + tid) * 4;
            #pragma unroll
            for (int j = 0; j < 4; ++j) {
                if (vals[j] >= T) {
                    int p = atomicAdd(&g_scnt[b], 1);
                    if (p < SCAP) {
                        g_surv_v[b * SCAP + p] = vals[j];
                        g_surv_i[b * SCAP + p] = sb + j;
                    }
                }
            }
        }
    }
}

// ---------------- K5b: final top-16 + softmax + proto gather ------------
__global__ void __launch_bounds__(128) k5b(const float* __restrict__ mem) {
    __shared__ float cv[SCAP];
    __shared__ int   ci[SCAP];
    __shared__ float selv[KTOP];
    __shared__ int   seli[KTOP];
    __shared__ float attn[KTOP];
    int b = blockIdx.x, tid = threadIdx.x, lane = tid & 31;
    int n = min(g_scnt[b], SCAP);

    for (int i = tid; i < n; i += 128) {
        cv[i] = g_surv_v[b * SCAP + i];
        ci[i] = g_surv_i[b * SCAP + i];
    }
    __syncthreads();

    if (tid < 32) {
        #pragma unroll 1
        for (int r = 0; r < KTOP; ++r) {
            float mv = -1e30f; int gi = 0x7fffffff; int mi = 0;
            for (int i = lane; i < n; i += 32) {
                float v = cv[i]; int idx = ci[i];
                if (v > mv || (v == mv && idx < gi)) { mv = v; gi = idx; mi = i; }
            }
            float bv = mv; int bgi = gi; int bmi = mi;
            #pragma unroll
            for (int off = 16; off; off >>= 1) {
                float ov  = __shfl_xor_sync(0xffffffffu, bv, off);
                int   ogi = __shfl_xor_sync(0xffffffffu, bgi, off);
                int   omi = __shfl_xor_sync(0xffffffffu, bmi, off);
                if (ov > bv || (ov == bv && ogi < bgi)) { bv = ov; bgi = ogi; bmi = omi; }
            }
            if (lane == 0) {
                selv[r] = bv; seli[r] = bgi;
                cv[bmi] = -1e30f;
            }
            __syncwarp();
        }
        if (lane == 0) {
            float mx = selv[0];
            float e[KTOP], ssum = 0.f;
            #pragma unroll
            for (int k = 0; k < KTOP; ++k) { e[k] = expf(selv[k] - mx); ssum += e[k]; }
            #pragma unroll
            for (int k = 0; k < KTOP; ++k) attn[k] = e[k] / ssum;
        }
    }
    __syncthreads();

    float acc = 0.f;
    #pragma unroll
    for (int k = 0; k < KTOP; ++k)
        acc = fmaf(attn[k], mem[(size_t)seli[k] * 128 + tid], acc);
    g_proto[b * 128 + tid] = acc;
}

// ---------------- K6: out = x + scale * proto ---------------------------
__global__ void __launch_bounds__(256) k6_add(const float* __restrict__ x,
                                              const float* __restrict__ scale_p,
                                              float* __restrict__ out) {
    __shared__ float pr[128];
    __shared__ float sc;
    int b = blockIdx.y;
    if (threadIdx.x < 128) pr[threadIdx.x] = g_proto[b * 128 + threadIdx.x];
    if (threadIdx.x == 0) sc = *scale_p;
    __syncthreads();

    float s = sc;
    const float4* xv = (const float4*)x;
    float4* ov = (float4*)out;
    size_t f0 = ((size_t)b * (NN * DD) + (size_t)blockIdx.x * 4096) >> 2;
    #pragma unroll
    for (int it = 0; it < 4; ++it) {
        size_t f = f0 + it * 256 + threadIdx.x;
        float4 v = xv[f];
        int d4 = (int)(f & 31);
        const float* p = &pr[d4 * 4];
        v.x = fmaf(s, p[0], v.x);
        v.y = fmaf(s, p[1], v.y);
        v.z = fmaf(s, p[2], v.z);
        v.w = fmaf(s, p[3], v.w);
        ov[f] = v;
    }
}

// ---------------- launch -------------------------------------------------
extern "C" void kernel_launch(void* const* d_in, const int* in_sizes, int n_in,
                              void* d_out, int out_size) {
    const float* x      = (const float*)d_in[0];
    const float* conv_w = (const float*)d_in[1];
    const float* conv_b = (const float*)d_in[2];
    const float* memory = (const float*)d_in[3];
    const float* scale  = (const float*)d_in[4];
    float* out = (float*)d_out;

    cudaFuncSetAttribute(k2_mma, cudaFuncAttributeMaxDynamicSharedMemorySize, K2_SMEM);
    cudaFuncSetAttribute(k4f, cudaFuncAttributeMaxDynamicSharedMemorySize, K4_SMEM);

    k2_mma<<<BB * 4, 256, K2_SMEM>>>(x, conv_w, conv_b);
    k3_q<<<BB, 128>>>();
    k4f<<<NBLK, 256, K4_SMEM>>>(memory);
    k5t<<<BB, 128>>>();
    dim3 g5s(NCH, BB);
    k5s<<<g5s, 256>>>();
    k5b<<<BB, 128>>>(memory);
    dim3 g6(128, BB);
    k6_add<<<g6, 256>>>(x, scale, out);
    (void)in_sizes; (void)n_in; (void)out_size;
}

// round 11
// speedup vs baseline: 1.5067x; 1.5067x over previous
#include <cuda_runtime.h>
#include <cuda_bf16.h>
#include <math.h>
#include <stdint.h>

#define BB 64
#define NN 4096
#define DD 128
#define SS 65536
#define KTOP 16
#define NCH 8                         // filter chunks per b
#define CHSZ (SS / NCH)               // 8192
#define NBLK 512                      // k4f blocks (128 s each)
#define SCAP 2560                     // survivor capacity (worst bound 2048+ties)

typedef unsigned long long ull;

// ---------------- scratch (device globals; allocation-free) ----------------
__device__ float g_qpart[BB * 4 * DD];   // per-CTA partial gelu sums
__device__ float g_qt[DD * BB];          // normalized q^T: [d][b]
__device__ float g_sim[(size_t)BB * SS]; // cosine sims                    (16 MB)
__device__ float g_proto[BB * DD];
__device__ float g_bmax[BB * NBLK];      // per-(b, k4f-block) max
__device__ float g_thr[BB];              // per-b threshold (16th of block maxes)
__device__ int   g_scnt[BB];             // per-b survivor count
__device__ float g_surv_v[BB * SCAP];
__device__ int   g_surv_i[BB * SCAP];

// ---------------- generic helpers ----------------
__device__ __forceinline__ ull ffma2(ull a, ull b, ull c) {
    ull d;
    asm("fma.rn.f32x2 %0, %1, %2, %3;" : "=l"(d) : "l"(a), "l"(b), "l"(c));
    return d;
}
__device__ __forceinline__ ull dup2(float x) {
    ull d;
    asm("mov.b64 %0, {%1, %1};" : "=l"(d) : "f"(x));
    return d;
}
__device__ __forceinline__ void unpack2(ull v, float& lo, float& hi) {
    asm("mov.b64 {%0, %1}, %2;" : "=f"(lo), "=f"(hi) : "l"(v));
}
// fast exact-enough gelu: erf via Abramowitz-Stegun 7.1.26 (|eps|<=1.5e-7)
__device__ __forceinline__ float gelu_exact(float z) {
    float x = z * 0.70710678118654752f;
    float ax = fabsf(x);
    float t = __fdividef(1.0f, fmaf(0.3275911f, ax, 1.0f));
    float p = t * fmaf(t, fmaf(t, fmaf(t, fmaf(t, 1.061405429f, -1.453152027f),
                                       1.421413741f), -0.284496736f), 0.254829592f);
    float e = __expf(-x * x);
    float er = copysignf(fmaf(-p, e, 1.0f), x);
    return 0.5f * z * (1.0f + er);
}
// split fp32 -> bf16 hi + bf16 lo (hi+lo represents v to ~2^-17)
__device__ __forceinline__ void bsplit(float v, uint16_t& h, uint16_t& l) {
    __nv_bfloat16 bh = __float2bfloat16_rn(v);
    float r = v - __bfloat162float(bh);
    __nv_bfloat16 bl = __float2bfloat16_rn(r);
    h = *(uint16_t*)&bh; l = *(uint16_t*)&bl;
}
__device__ __forceinline__ uint32_t bpack(float lo, float hi) {
    uint32_t r;
    asm("cvt.rn.bf16x2.f32 %0, %1, %2;" : "=r"(r) : "f"(hi), "f"(lo));
    return r;
}

// bf16 m16n8k16 mma.sync
__device__ __forceinline__ void mma_bf16(float* c, uint32_t a0, uint32_t a1,
                                         uint32_t a2, uint32_t a3,
                                         uint32_t b0, uint32_t b1) {
    asm volatile(
        "mma.sync.aligned.m16n8k16.row.col.f32.bf16.bf16.f32 "
        "{%0,%1,%2,%3}, {%4,%5,%6,%7}, {%8,%9}, {%0,%1,%2,%3};"
        : "+f"(c[0]), "+f"(c[1]), "+f"(c[2]), "+f"(c[3])
        : "r"(a0), "r"(a1), "r"(a2), "r"(a3), "r"(b0), "r"(b1));
}

// ---------------- K2: bf16 hi/lo-W mma conv1d+GeLU+sum-over-n -----------
// grid 256 = (b, quarter-n), 128 threads (4 warps = 4 e-quarters),
// tile 64n x 128e, 32 steps (16 tiles x 2 k-halves), 2-stage A ring,
// 2 independent CTAs/SM (no reg cap issue: 256 thr/SM -> 256 regs/thr).
#define WS16 136                     // bf16 per W row (128 + 8 pad)
#define AS16 72                      // bf16 per A row (64 + 8 pad)
#define AB16 (64 * AS16)             // 4608 bf16 per A buffer (9216 B)
#define O_W    0                     // Whi: 34816 B
#define O_WLO  34816                 // Wlo: 34816 B
#define O_A    69632                 // 2 * 9216 = 18432 B
#define O_BIAS 88064                 // 512 B
#define O_RED  88576                 // 512 B
#define K2_SMEM 89600

__global__ void __launch_bounds__(128, 2) k2_mma(const float* __restrict__ x,
                                                 const float* __restrict__ w,
                                                 const float* __restrict__ bias) {
    extern __shared__ char smc[];
    uint16_t* ws    = (uint16_t*)(smc + O_W);
    uint16_t* wl    = (uint16_t*)(smc + O_WLO);
    uint16_t* ab    = (uint16_t*)(smc + O_A);
    float*    sbias = (float*)(smc + O_BIAS);
    float*    red   = (float*)(smc + O_RED);

    int tid = threadIdx.x, wid = tid >> 5, lane = tid & 31;
    int g = lane >> 2, kc = lane & 3;
    int cta = blockIdx.x, b = cta >> 2, quarter = cta & 3;
    const float* xb = x + ((size_t)b * NN + (size_t)quarter * 1024) * DD;

    // ---- stage W as bf16 hi/lo [e][k] ----
    for (int i = tid; i < 4096; i += 128) {      // float4 over [128e][32]
        float4 v = ((const float4*)w)[i];
        int e = i >> 5, d0 = (i & 31) * 4;
        uint16_t h[4], l[4];
        bsplit(v.x, h[0], l[0]); bsplit(v.y, h[1], l[1]);
        bsplit(v.z, h[2], l[2]); bsplit(v.w, h[3], l[3]);
        *(uint2*)&ws[e * WS16 + d0] = make_uint2((uint32_t)h[0] | ((uint32_t)h[1] << 16),
                                                 (uint32_t)h[2] | ((uint32_t)h[3] << 16));
        *(uint2*)&wl[e * WS16 + d0] = make_uint2((uint32_t)l[0] | ((uint32_t)l[1] << 16),
                                                 (uint32_t)l[2] | ((uint32_t)l[3] << 16));
    }
    sbias[tid] = bias[tid];

    int ew = wid * 32;                           // warp e-quarter

    float c[4][4][4];
    #pragma unroll
    for (int mf = 0; mf < 4; ++mf)
        #pragma unroll
        for (int ef = 0; ef < 4; ++ef)
            #pragma unroll
            for (int q = 0; q < 4; ++q) c[mf][ef][q] = 0.f;
    float es[8];
    #pragma unroll
    for (int s = 0; s < 8; ++s) es[s] = 0.f;

    float4 r8[8];
    auto ldg = [&](int gstep) {
        int t = gstep >> 1, h = gstep & 1;
        const float* base = xb + (size_t)t * (64 * DD) + h * 64;
        #pragma unroll
        for (int j = 0; j < 8; ++j) {
            int idx = j * 128 + tid;             // 0..1023
            int row = idx >> 4, seg = idx & 15;
            r8[j] = *(const float4*)(base + (size_t)row * DD + seg * 4);
        }
    };
    auto sts = [&](int buf) {
        uint16_t* d = ab + buf * AB16;
        #pragma unroll
        for (int j = 0; j < 8; ++j) {
            int idx = j * 128 + tid;
            int row = idx >> 4, seg = idx & 15;
            uint2 p = make_uint2(bpack(r8[j].x, r8[j].y), bpack(r8[j].z, r8[j].w));
            *(uint2*)&d[row * AS16 + seg * 4] = p;
        }
    };

    ldg(0); sts(0);
    ldg(1);
    __syncthreads();                 // W + bias + buf0 visible

    float bs[8];
    #pragma unroll
    for (int ef = 0; ef < 4; ++ef) {
        bs[ef * 2 + 0] = sbias[ew + ef * 8 + 2 * kc + 0];
        bs[ef * 2 + 1] = sbias[ew + ef * 8 + 2 * kc + 1];
    }

    #pragma unroll 1
    for (int step = 0; step < 32; ++step) {
        if (step < 31) sts((step + 1) & 1);      // regs for step+1 -> ring
        if (step < 30) ldg(step + 2);            // prefetch step+2

        const uint16_t* A = ab + (step & 1) * AB16;
        int kg0 = (step & 1) * 64;               // k offset into W
        #pragma unroll
        for (int ks = 0; ks < 4; ++ks) {
            int kb = ks * 16;
            uint32_t a[4][4];
            #pragma unroll
            for (int mf = 0; mf < 4; ++mf) {
                int r = g + mf * 16;
                a[mf][0] = *(const uint32_t*)&A[r * AS16 + kb + 2 * kc];
                a[mf][1] = *(const uint32_t*)&A[(r + 8) * AS16 + kb + 2 * kc];
                a[mf][2] = *(const uint32_t*)&A[r * AS16 + kb + 2 * kc + 8];
                a[mf][3] = *(const uint32_t*)&A[(r + 8) * AS16 + kb + 2 * kc + 8];
            }
            #pragma unroll
            for (int ef = 0; ef < 4; ++ef) {
                int e = ew + ef * 8 + g;
                uint32_t b0 = *(const uint32_t*)&ws[e * WS16 + kg0 + kb + 2 * kc];
                uint32_t b1 = *(const uint32_t*)&ws[e * WS16 + kg0 + kb + 2 * kc + 8];
                uint32_t c0 = *(const uint32_t*)&wl[e * WS16 + kg0 + kb + 2 * kc];
                uint32_t c1 = *(const uint32_t*)&wl[e * WS16 + kg0 + kb + 2 * kc + 8];
                #pragma unroll
                for (int mf = 0; mf < 4; ++mf) {
                    mma_bf16(c[mf][ef], a[mf][0], a[mf][1], a[mf][2], a[mf][3], b0, b1);
                    mma_bf16(c[mf][ef], a[mf][0], a[mf][1], a[mf][2], a[mf][3], c0, c1);
                }
            }
        }

        if ((step & 1) == 1) {                   // tile done: gelu + accumulate
            #pragma unroll
            for (int mf = 0; mf < 4; ++mf)
                #pragma unroll
                for (int ef = 0; ef < 4; ++ef)
                    #pragma unroll
                    for (int q = 0; q < 4; ++q) {
                        int s = ef * 2 + (q & 1);
                        es[s] += gelu_exact(c[mf][ef][q] + bs[s]);
                        c[mf][ef][q] = 0.f;
                    }
        }
        __syncthreads();                         // publish sts, guard ring reuse
    }

    // reduce over rows (g) within warp; warps own disjoint e-columns
    #pragma unroll
    for (int off = 16; off >= 4; off >>= 1)
        #pragma unroll
        for (int s = 0; s < 8; ++s)
            es[s] += __shfl_xor_sync(0xffffffffu, es[s], off);
    if (g == 0) {
        #pragma unroll
        for (int s = 0; s < 8; ++s) {
            int ecol = ew + (s >> 1) * 8 + 2 * kc + (s & 1);
            red[ecol] = es[s];
        }
    }
    __syncthreads();
    g_qpart[(b * 4 + quarter) * 128 + tid] = red[tid];
}

// ---------------- K3: finalize q + normalize + transpose ----------------
__global__ void k3_q() {
    int b = blockIdx.x, e = threadIdx.x;
    float q = g_qpart[b * 512 + e] + g_qpart[b * 512 + 128 + e] +
              g_qpart[b * 512 + 256 + e] + g_qpart[b * 512 + 384 + e];
    __shared__ float sr[128];
    sr[e] = q * q;
    __syncthreads();
    for (int off = 64; off; off >>= 1) {
        if (e < off) sr[e] += sr[e + off];
        __syncthreads();
    }
    float inv = 1.0f / fmaxf(sqrtf(sr[0]), 1e-12f);
    g_qt[e * 64 + b] = q * inv;
}

// ---------------- K4f: fused normalize + sim GEMM + block maxes ---------
#define S4_QS  0
#define S4_MT  8192
#define S4_TL  24576
#define S4_INV 32832
#define K4_SMEM ((32832 + 64) * 4)   // 131584 bytes

__global__ void __launch_bounds__(256, 1) k4f(const float* __restrict__ mem) {
    extern __shared__ float s4[];
    float* qs   = s4 + S4_QS;
    float* mt   = s4 + S4_MT;
    float* tile = s4 + S4_TL;
    float* inv  = s4 + S4_INV;
    int tid = threadIdx.x;
    int s0 = blockIdx.x * 128;

    for (int i = tid; i < 8192; i += 256) qs[i] = g_qt[i];

    #pragma unroll 1
    for (int half = 0; half < 2; ++half) {
        int c = tid & 31, r0 = tid >> 5;
        #pragma unroll
        for (int it = 0; it < 8; ++it) {
            int r = r0 + it * 8;
            float4 v = *(const float4*)&mem[(size_t)(s0 + half * 64 + r) * 128 + c * 4];
            tile[r * 129 + c * 4 + 0] = v.x; tile[r * 129 + c * 4 + 1] = v.y;
            tile[r * 129 + c * 4 + 2] = v.z; tile[r * 129 + c * 4 + 3] = v.w;
        }
        __syncthreads();
        if (tid < 64) {
            float acc = 0.f;
            #pragma unroll 8
            for (int k = 0; k < 128; ++k) { float t = tile[tid * 129 + k]; acc = fmaf(t, t, acc); }
            inv[tid] = 1.0f / fmaxf(sqrtf(acc), 1e-12f);
        }
        __syncthreads();
        int r = tid & 63, kg = tid >> 6;
        float iv = inv[r];
        #pragma unroll
        for (int it = 0; it < 32; ++it) {
            int k = kg + it * 4;
            mt[k * 128 + half * 64 + r] = tile[r * 129 + k] * iv;
        }
        __syncthreads();
    }

    int tm = tid >> 4, tn = tid & 15;
    ull acc[4][4];
    #pragma unroll
    for (int i = 0; i < 4; ++i)
        #pragma unroll
        for (int j = 0; j < 4; ++j) acc[i][j] = 0ull;

    #pragma unroll 8
    for (int k = 0; k < 128; ++k) {
        float4 av = *(const float4*)&qs[k * 64 + tm * 4];
        ull a0 = dup2(av.x), a1 = dup2(av.y), a2 = dup2(av.z), a3 = dup2(av.w);
        const float* mrow = mt + k * 128;
        #pragma unroll
        for (int gg = 0; gg < 2; ++gg) {
            ulonglong2 bv = *(const ulonglong2*)(mrow + (tn + gg * 16) * 4);
            acc[0][gg * 2 + 0] = ffma2(a0, bv.x, acc[0][gg * 2 + 0]);
            acc[0][gg * 2 + 1] = ffma2(a0, bv.y, acc[0][gg * 2 + 1]);
            acc[1][gg * 2 + 0] = ffma2(a1, bv.x, acc[1][gg * 2 + 0]);
            acc[1][gg * 2 + 1] = ffma2(a1, bv.y, acc[1][gg * 2 + 1]);
            acc[2][gg * 2 + 0] = ffma2(a2, bv.x, acc[2][gg * 2 + 0]);
            acc[2][gg * 2 + 1] = ffma2(a2, bv.y, acc[2][gg * 2 + 1]);
            acc[3][gg * 2 + 0] = ffma2(a3, bv.x, acc[3][gg * 2 + 0]);
            acc[3][gg * 2 + 1] = ffma2(a3, bv.y, acc[3][gg * 2 + 1]);
        }
    }
    #pragma unroll
    for (int i = 0; i < 4; ++i) {
        int b = tm * 4 + i;
        float4 o0, o1;
        unpack2(acc[i][0], o0.x, o0.y);
        unpack2(acc[i][1], o0.z, o0.w);
        unpack2(acc[i][2], o1.x, o1.y);
        unpack2(acc[i][3], o1.z, o1.w);
        *(float4*)&g_sim[(size_t)b * SS + s0 + tn * 4] = o0;
        *(float4*)&g_sim[(size_t)b * SS + s0 + (tn + 16) * 4] = o1;
        float mx = fmaxf(fmaxf(fmaxf(o0.x, o0.y), fmaxf(o0.z, o0.w)),
                         fmaxf(fmaxf(o1.x, o1.y), fmaxf(o1.z, o1.w)));
        #pragma unroll
        for (int off = 1; off < 16; off <<= 1)
            mx = fmaxf(mx, __shfl_xor_sync(0xffffffffu, mx, off));
        if (tn == 0) g_bmax[b * NBLK + blockIdx.x] = mx;
    }
}

// ---------------- K5t: per-b threshold = 16th largest of block maxes ----
// Parallel: 4 warps each select top-16 of their 128 values; warp0 takes
// the 16th largest of the 64 candidates (= exact 16th of all 512).
__global__ void __launch_bounds__(128) k5t() {
    __shared__ float sm5[NBLK];
    __shared__ float wv[4 * KTOP];
    int b = blockIdx.x, tid = threadIdx.x, wid = tid >> 5, lane = tid & 31;
    for (int i = tid; i < NBLK; i += 128) sm5[i] = g_bmax[b * NBLK + i];
    __syncthreads();

    {
        float lv[4];
        #pragma unroll
        for (int j = 0; j < 4; ++j) lv[j] = sm5[wid * 128 + lane * 4 + j];
        #pragma unroll 1
        for (int r = 0; r < KTOP; ++r) {
            float mv = lv[0]; int lm = 0;
            #pragma unroll
            for (int j = 1; j < 4; ++j) if (lv[j] > mv) { mv = lv[j]; lm = j; }
            float bv = mv; int bl = lane;
            #pragma unroll
            for (int off = 16; off; off >>= 1) {
                float ov = __shfl_xor_sync(0xffffffffu, bv, off);
                int ol = __shfl_xor_sync(0xffffffffu, bl, off);
                if (ov > bv || (ov == bv && ol < bl)) { bv = ov; bl = ol; }
            }
            if (lane == bl) {
                #pragma unroll
                for (int j = 0; j < 4; ++j) if (j == lm) lv[j] = -1e30f;
            }
            if (lane == 0) wv[wid * KTOP + r] = bv;
        }
    }
    __syncthreads();

    if (wid == 0) {
        float lv[2];
        lv[0] = wv[lane * 2]; lv[1] = wv[lane * 2 + 1];
        float T = 0.f;
        #pragma unroll 1
        for (int r = 0; r < KTOP; ++r) {
            float mv = lv[0]; int lm = 0;
            if (lv[1] > mv) { mv = lv[1]; lm = 1; }
            float bv = mv; int bl = lane;
            #pragma unroll
            for (int off = 16; off; off >>= 1) {
                float ov = __shfl_xor_sync(0xffffffffu, bv, off);
                int ol = __shfl_xor_sync(0xffffffffu, bl, off);
                if (ov > bv || (ov == bv && ol < bl)) { bv = ov; bl = ol; }
            }
            if (lane == bl) { if (lm == 0) lv[0] = -1e30f; else lv[1] = -1e30f; }
            T = bv;
        }
        if (lane == 0) { g_thr[b] = T; g_scnt[b] = 0; }
    }
}

// ---------------- K5s: stream filter (no selection) ---------------------
__global__ void __launch_bounds__(256) k5s() {
    int b = blockIdx.y, ch = blockIdx.x;
    int tid = threadIdx.x;
    float T = g_thr[b];
    const float4* rowv = (const float4*)(g_sim + (size_t)b * SS + (size_t)ch * CHSZ);
    int base = ch * CHSZ;
    #pragma unroll
    for (int it = 0; it < 8; ++it) {
        float4 v = rowv[it * 256 + tid];
        float vm = fmaxf(fmaxf(v.x, v.y), fmaxf(v.z, v.w));
        if (vm >= T) {
            float vals[4] = {v.x, v.y, v.z, v.w};
            int sb = base + (it * 256 + tid) * 4;
            #pragma unroll
            for (int j = 0; j < 4; ++j) {
                if (vals[j] >= T) {
                    int p = atomicAdd(&g_scnt[b], 1);
                    if (p < SCAP) {
                        g_surv_v[b * SCAP + p] = vals[j];
                        g_surv_i[b * SCAP + p] = sb + j;
                    }
                }
            }
        }
    }
}

// ---------------- K5b: final top-16 + softmax + proto gather ------------
__global__ void __launch_bounds__(128) k5b(const float* __restrict__ mem) {
    __shared__ float cv[SCAP];
    __shared__ int   ci[SCAP];
    __shared__ float selv[KTOP];
    __shared__ int   seli[KTOP];
    __shared__ float attn[KTOP];
    int b = blockIdx.x, tid = threadIdx.x, lane = tid & 31;
    int n = min(g_scnt[b], SCAP);

    for (int i = tid; i < n; i += 128) {
        cv[i] = g_surv_v[b * SCAP + i];
        ci[i] = g_surv_i[b * SCAP + i];
    }
    __syncthreads();

    if (tid < 32) {
        #pragma unroll 1
        for (int r = 0; r < KTOP; ++r) {
            float mv = -1e30f; int gi = 0x7fffffff; int mi = 0;
            for (int i = lane; i < n; i += 32) {
                float v = cv[i]; int idx = ci[i];
                if (v > mv || (v == mv && idx < gi)) { mv = v; gi = idx; mi = i; }
            }
            float bv = mv; int bgi = gi; int bmi = mi;
            #pragma unroll
            for (int off = 16; off; off >>= 1) {
                float ov  = __shfl_xor_sync(0xffffffffu, bv, off);
                int   ogi = __shfl_xor_sync(0xffffffffu, bgi, off);
                int   omi = __shfl_xor_sync(0xffffffffu, bmi, off);
                if (ov > bv || (ov == bv && ogi < bgi)) { bv = ov; bgi = ogi; bmi = omi; }
            }
            if (lane == 0) {
                selv[r] = bv; seli[r] = bgi;
                cv[bmi] = -1e30f;
            }
            __syncwarp();
        }
        if (lane == 0) {
            float mx = selv[0];
            float e[KTOP], ssum = 0.f;
            #pragma unroll
            for (int k = 0; k < KTOP; ++k) { e[k] = expf(selv[k] - mx); ssum += e[k]; }
            #pragma unroll
            for (int k = 0; k < KTOP; ++k) attn[k] = e[k] / ssum;
        }
    }
    __syncthreads();

    float acc = 0.f;
    #pragma unroll
    for (int k = 0; k < KTOP; ++k)
        acc = fmaf(attn[k], mem[(size_t)seli[k] * 128 + tid], acc);
    g_proto[b * 128 + tid] = acc;
}

// ---------------- K6: out = x + scale * proto ---------------------------
__global__ void __launch_bounds__(256) k6_add(const float* __restrict__ x,
                                              const float* __restrict__ scale_p,
                                              float* __restrict__ out) {
    __shared__ float pr[128];
    __shared__ float sc;
    int b = blockIdx.y;
    if (threadIdx.x < 128) pr[threadIdx.x] = g_proto[b * 128 + threadIdx.x];
    if (threadIdx.x == 0) sc = *scale_p;
    __syncthreads();

    float s = sc;
    const float4* xv = (const float4*)x;
    float4* ov = (float4*)out;
    size_t f0 = ((size_t)b * (NN * DD) + (size_t)blockIdx.x * 4096) >> 2;
    #pragma unroll
    for (int it = 0; it < 4; ++it) {
        size_t f = f0 + it * 256 + threadIdx.x;
        float4 v = xv[f];
        int d4 = (int)(f & 31);
        const float* p = &pr[d4 * 4];
        v.x = fmaf(s, p[0], v.x);
        v.y = fmaf(s, p[1], v.y);
        v.z = fmaf(s, p[2], v.z);
        v.w = fmaf(s, p[3], v.w);
        ov[f] = v;
    }
}

// ---------------- launch -------------------------------------------------
extern "C" void kernel_launch(void* const* d_in, const int* in_sizes, int n_in,
                              void* d_out, int out_size) {
    const float* x      = (const float*)d_in[0];
    const float* conv_w = (const float*)d_in[1];
    const float* conv_b = (const float*)d_in[2];
    const float* memory = (const float*)d_in[3];
    const float* scale  = (const float*)d_in[4];
    float* out = (float*)d_out;

    cudaFuncSetAttribute(k2_mma, cudaFuncAttributeMaxDynamicSharedMemorySize, K2_SMEM);
    cudaFuncSetAttribute(k4f, cudaFuncAttributeMaxDynamicSharedMemorySize, K4_SMEM);

    k2_mma<<<BB * 4, 128, K2_SMEM>>>(x, conv_w, conv_b);
    k3_q<<<BB, 128>>>();
    k4f<<<NBLK, 256, K4_SMEM>>>(memory);
    k5t<<<BB, 128>>>();
    dim3 g5s(NCH, BB);
    k5s<<<g5s, 256>>>();
    k5b<<<BB, 128>>>(memory);
    dim3 g6(128, BB);
    k6_add<<<g6, 256>>>(x, scale, out);
    (void)in_sizes; (void)n_in; (void)out_size;
}

// round 12
// speedup vs baseline: 1.6514x; 1.0960x over previous
#include <cuda_runtime.h>
#include <cuda_fp16.h>
#include <math.h>
#include <stdint.h>

#define BB 64
#define NN 4096
#define DD 128
#define SS 65536
#define KTOP 16
#define NCH 8                         // filter chunks per b
#define CHSZ (SS / NCH)               // 8192
#define NBLK 512                      // k4f blocks (128 s each)
#define SCAP 2560                     // survivor capacity

typedef unsigned long long ull;

// ---------------- scratch (device globals; allocation-free) ----------------
__device__ float g_qpart[BB * 4 * DD];   // per-CTA partial gelu sums
__device__ float g_qt[DD * BB];          // normalized q^T: [d][b]
__device__ float g_sim[(size_t)BB * SS]; // cosine sims                    (16 MB)
__device__ float g_proto[BB * DD];
__device__ float g_bmax[BB * NBLK];      // per-(b, k4f-block) max
__device__ int   g_scnt[BB];             // per-b survivor count
__device__ float g_surv_v[BB * SCAP];
__device__ int   g_surv_i[BB * SCAP];

// ---------------- generic helpers ----------------
__device__ __forceinline__ ull ffma2(ull a, ull b, ull c) {
    ull d;
    asm("fma.rn.f32x2 %0, %1, %2, %3;" : "=l"(d) : "l"(a), "l"(b), "l"(c));
    return d;
}
__device__ __forceinline__ ull dup2(float x) {
    ull d;
    asm("mov.b64 %0, {%1, %1};" : "=l"(d) : "f"(x));
    return d;
}
__device__ __forceinline__ void unpack2(ull v, float& lo, float& hi) {
    asm("mov.b64 {%0, %1}, %2;" : "=f"(lo), "=f"(hi) : "l"(v));
}
// fast exact-enough gelu: erf via Abramowitz-Stegun 7.1.26 (|eps|<=1.5e-7)
__device__ __forceinline__ float gelu_exact(float z) {
    float x = z * 0.70710678118654752f;
    float ax = fabsf(x);
    float t = __fdividef(1.0f, fmaf(0.3275911f, ax, 1.0f));
    float p = t * fmaf(t, fmaf(t, fmaf(t, fmaf(t, 1.061405429f, -1.453152027f),
                                       1.421413741f), -0.284496736f), 0.254829592f);
    float e = __expf(-x * x);
    float er = copysignf(fmaf(-p, e, 1.0f), x);
    return 0.5f * z * (1.0f + er);
}
// pack two fp32 -> f16x2 (lo = first arg, hi = second)
__device__ __forceinline__ uint32_t hpack(float lo, float hi) {
    uint32_t r;
    asm("cvt.rn.f16x2.f32 %0, %1, %2;" : "=r"(r) : "f"(hi), "f"(lo));
    return r;
}

// fp16 m16n8k16 mma.sync
__device__ __forceinline__ void mma_f16(float* c, uint32_t a0, uint32_t a1,
                                        uint32_t a2, uint32_t a3,
                                        uint32_t b0, uint32_t b1) {
    asm volatile(
        "mma.sync.aligned.m16n8k16.row.col.f32.f16.f16.f32 "
        "{%0,%1,%2,%3}, {%4,%5,%6,%7}, {%8,%9}, {%0,%1,%2,%3};"
        : "+f"(c[0]), "+f"(c[1]), "+f"(c[2]), "+f"(c[3])
        : "r"(a0), "r"(a1), "r"(a2), "r"(a3), "r"(b0), "r"(b1));
}

// ---------------- K2: fp16 mma conv1d+GeLU+sum-over-n -------------------
// grid 256 = (b, quarter-n), 128 threads (4 warps = 4 e-quarters),
// tile 64n x 128e, 32 steps, 2-stage A ring, 2 CTAs/SM.
#define WS16 136                     // f16 per W row (128 + 8 pad)
#define AS16 72                      // f16 per A row (64 + 8 pad)
#define AB16 (64 * AS16)             // 4608 f16 per A buffer (9216 B)
#define O_W    0                     // 34816 B
#define O_A    34816                 // 2 * 9216 = 18432 B
#define O_BIAS 53248                 // 512 B
#define O_RED  53760                 // 512 B
#define K2_SMEM 54784

__global__ void __launch_bounds__(128, 2) k2_mma(const float* __restrict__ x,
                                                 const float* __restrict__ w,
                                                 const float* __restrict__ bias) {
    extern __shared__ char smc[];
    uint16_t* ws    = (uint16_t*)(smc + O_W);
    uint16_t* ab    = (uint16_t*)(smc + O_A);
    float*    sbias = (float*)(smc + O_BIAS);
    float*    red   = (float*)(smc + O_RED);

    int tid = threadIdx.x, wid = tid >> 5, lane = tid & 31;
    int g = lane >> 2, kc = lane & 3;
    int cta = blockIdx.x, b = cta >> 2, quarter = cta & 3;
    const float* xb = x + ((size_t)b * NN + (size_t)quarter * 1024) * DD;

    // ---- stage W as fp16 [e][k] ----
    for (int i = tid; i < 4096; i += 128) {      // float4 over [128e][32]
        float4 v = ((const float4*)w)[i];
        int e = i >> 5, d0 = (i & 31) * 4;
        *(uint2*)&ws[e * WS16 + d0] = make_uint2(hpack(v.x, v.y), hpack(v.z, v.w));
    }
    sbias[tid] = bias[tid];

    int ew = wid * 32;                           // warp e-quarter

    float c[4][4][4];
    #pragma unroll
    for (int mf = 0; mf < 4; ++mf)
        #pragma unroll
        for (int ef = 0; ef < 4; ++ef)
            #pragma unroll
            for (int q = 0; q < 4; ++q) c[mf][ef][q] = 0.f;
    float es[8];
    #pragma unroll
    for (int s = 0; s < 8; ++s) es[s] = 0.f;

    float4 r8[8];
    auto ldg = [&](int gstep) {
        int t = gstep >> 1, h = gstep & 1;
        const float* base = xb + (size_t)t * (64 * DD) + h * 64;
        #pragma unroll
        for (int j = 0; j < 8; ++j) {
            int idx = j * 128 + tid;             // 0..1023
            int row = idx >> 4, seg = idx & 15;
            r8[j] = *(const float4*)(base + (size_t)row * DD + seg * 4);
        }
    };
    auto sts = [&](int buf) {
        uint16_t* d = ab + buf * AB16;
        #pragma unroll
        for (int j = 0; j < 8; ++j) {
            int idx = j * 128 + tid;
            int row = idx >> 4, seg = idx & 15;
            *(uint2*)&d[row * AS16 + seg * 4] =
                make_uint2(hpack(r8[j].x, r8[j].y), hpack(r8[j].z, r8[j].w));
        }
    };

    ldg(0); sts(0);
    ldg(1);
    __syncthreads();                 // W + bias + buf0 visible

    float bs[8];
    #pragma unroll
    for (int ef = 0; ef < 4; ++ef) {
        bs[ef * 2 + 0] = sbias[ew + ef * 8 + 2 * kc + 0];
        bs[ef * 2 + 1] = sbias[ew + ef * 8 + 2 * kc + 1];
    }

    #pragma unroll 1
    for (int step = 0; step < 32; ++step) {
        if (step < 31) sts((step + 1) & 1);      // regs for step+1 -> ring
        if (step < 30) ldg(step + 2);            // prefetch step+2

        const uint16_t* A = ab + (step & 1) * AB16;
        int kg0 = (step & 1) * 64;               // k offset into W
        #pragma unroll
        for (int ks = 0; ks < 4; ++ks) {
            int kb = ks * 16;
            uint32_t a[4][4];
            #pragma unroll
            for (int mf = 0; mf < 4; ++mf) {
                int r = g + mf * 16;
                a[mf][0] = *(const uint32_t*)&A[r * AS16 + kb + 2 * kc];
                a[mf][1] = *(const uint32_t*)&A[(r + 8) * AS16 + kb + 2 * kc];
                a[mf][2] = *(const uint32_t*)&A[r * AS16 + kb + 2 * kc + 8];
                a[mf][3] = *(const uint32_t*)&A[(r + 8) * AS16 + kb + 2 * kc + 8];
            }
            #pragma unroll
            for (int ef = 0; ef < 4; ++ef) {
                int e = ew + ef * 8 + g;
                uint32_t b0 = *(const uint32_t*)&ws[e * WS16 + kg0 + kb + 2 * kc];
                uint32_t b1 = *(const uint32_t*)&ws[e * WS16 + kg0 + kb + 2 * kc + 8];
                #pragma unroll
                for (int mf = 0; mf < 4; ++mf)
                    mma_f16(c[mf][ef], a[mf][0], a[mf][1], a[mf][2], a[mf][3], b0, b1);
            }
        }

        if ((step & 1) == 1) {                   // tile done: gelu + accumulate
            #pragma unroll
            for (int mf = 0; mf < 4; ++mf)
                #pragma unroll
                for (int ef = 0; ef < 4; ++ef)
                    #pragma unroll
                    for (int q = 0; q < 4; ++q) {
                        int s = ef * 2 + (q & 1);
                        es[s] += gelu_exact(c[mf][ef][q] + bs[s]);
                        c[mf][ef][q] = 0.f;
                    }
        }
        __syncthreads();                         // publish sts, guard ring reuse
    }

    // reduce over rows (g) within warp; warps own disjoint e-columns
    #pragma unroll
    for (int off = 16; off >= 4; off >>= 1)
        #pragma unroll
        for (int s = 0; s < 8; ++s)
            es[s] += __shfl_xor_sync(0xffffffffu, es[s], off);
    if (g == 0) {
        #pragma unroll
        for (int s = 0; s < 8; ++s) {
            int ecol = ew + (s >> 1) * 8 + 2 * kc + (s & 1);
            red[ecol] = es[s];
        }
    }
    __syncthreads();
    g_qpart[(b * 4 + quarter) * 128 + tid] = red[tid];
}

// ---------------- K3: finalize q + normalize + transpose ----------------
__global__ void k3_q() {
    int b = blockIdx.x, e = threadIdx.x;
    float q = g_qpart[b * 512 + e] + g_qpart[b * 512 + 128 + e] +
              g_qpart[b * 512 + 256 + e] + g_qpart[b * 512 + 384 + e];
    __shared__ float sr[128];
    sr[e] = q * q;
    __syncthreads();
    for (int off = 64; off; off >>= 1) {
        if (e < off) sr[e] += sr[e + off];
        __syncthreads();
    }
    float inv = 1.0f / fmaxf(sqrtf(sr[0]), 1e-12f);
    g_qt[e * 64 + b] = q * inv;
}

// ---------------- K4f: fused normalize + sim GEMM + block maxes ---------
#define S4_QS  0
#define S4_MT  8192
#define S4_TL  24576
#define S4_INV 32832
#define K4_SMEM ((32832 + 64) * 4)   // 131584 bytes

__global__ void __launch_bounds__(256, 1) k4f(const float* __restrict__ mem) {
    extern __shared__ float s4[];
    float* qs   = s4 + S4_QS;
    float* mt   = s4 + S4_MT;
    float* tile = s4 + S4_TL;
    float* inv  = s4 + S4_INV;
    int tid = threadIdx.x;
    int s0 = blockIdx.x * 128;

    if (blockIdx.x == 0 && tid < BB) g_scnt[tid] = 0;   // reset for k5s

    for (int i = tid; i < 8192; i += 256) qs[i] = g_qt[i];

    #pragma unroll 1
    for (int half = 0; half < 2; ++half) {
        int c = tid & 31, r0 = tid >> 5;
        #pragma unroll
        for (int it = 0; it < 8; ++it) {
            int r = r0 + it * 8;
            float4 v = *(const float4*)&mem[(size_t)(s0 + half * 64 + r) * 128 + c * 4];
            tile[r * 129 + c * 4 + 0] = v.x; tile[r * 129 + c * 4 + 1] = v.y;
            tile[r * 129 + c * 4 + 2] = v.z; tile[r * 129 + c * 4 + 3] = v.w;
        }
        __syncthreads();
        if (tid < 64) {
            float acc = 0.f;
            #pragma unroll 8
            for (int k = 0; k < 128; ++k) { float t = tile[tid * 129 + k]; acc = fmaf(t, t, acc); }
            inv[tid] = 1.0f / fmaxf(sqrtf(acc), 1e-12f);
        }
        __syncthreads();
        int r = tid & 63, kg = tid >> 6;
        float iv = inv[r];
        #pragma unroll
        for (int it = 0; it < 32; ++it) {
            int k = kg + it * 4;
            mt[k * 128 + half * 64 + r] = tile[r * 129 + k] * iv;
        }
        __syncthreads();
    }

    int tm = tid >> 4, tn = tid & 15;
    ull acc[4][4];
    #pragma unroll
    for (int i = 0; i < 4; ++i)
        #pragma unroll
        for (int j = 0; j < 4; ++j) acc[i][j] = 0ull;

    #pragma unroll 8
    for (int k = 0; k < 128; ++k) {
        float4 av = *(const float4*)&qs[k * 64 + tm * 4];
        ull a0 = dup2(av.x), a1 = dup2(av.y), a2 = dup2(av.z), a3 = dup2(av.w);
        const float* mrow = mt + k * 128;
        #pragma unroll
        for (int gg = 0; gg < 2; ++gg) {
            ulonglong2 bv = *(const ulonglong2*)(mrow + (tn + gg * 16) * 4);
            acc[0][gg * 2 + 0] = ffma2(a0, bv.x, acc[0][gg * 2 + 0]);
            acc[0][gg * 2 + 1] = ffma2(a0, bv.y, acc[0][gg * 2 + 1]);
            acc[1][gg * 2 + 0] = ffma2(a1, bv.x, acc[1][gg * 2 + 0]);
            acc[1][gg * 2 + 1] = ffma2(a1, bv.y, acc[1][gg * 2 + 1]);
            acc[2][gg * 2 + 0] = ffma2(a2, bv.x, acc[2][gg * 2 + 0]);
            acc[2][gg * 2 + 1] = ffma2(a2, bv.y, acc[2][gg * 2 + 1]);
            acc[3][gg * 2 + 0] = ffma2(a3, bv.x, acc[3][gg * 2 + 0]);
            acc[3][gg * 2 + 1] = ffma2(a3, bv.y, acc[3][gg * 2 + 1]);
        }
    }
    #pragma unroll
    for (int i = 0; i < 4; ++i) {
        int b = tm * 4 + i;
        float4 o0, o1;
        unpack2(acc[i][0], o0.x, o0.y);
        unpack2(acc[i][1], o0.z, o0.w);
        unpack2(acc[i][2], o1.x, o1.y);
        unpack2(acc[i][3], o1.z, o1.w);
        *(float4*)&g_sim[(size_t)b * SS + s0 + tn * 4] = o0;
        *(float4*)&g_sim[(size_t)b * SS + s0 + (tn + 16) * 4] = o1;
        float mx = fmaxf(fmaxf(fmaxf(o0.x, o0.y), fmaxf(o0.z, o0.w)),
                         fmaxf(fmaxf(o1.x, o1.y), fmaxf(o1.z, o1.w)));
        #pragma unroll
        for (int off = 1; off < 16; off <<= 1)
            mx = fmaxf(mx, __shfl_xor_sync(0xffffffffu, mx, off));
        if (tn == 0) g_bmax[b * NBLK + blockIdx.x] = mx;
    }
}

// ---------------- K5s: inline threshold + stream filter -----------------
// T = min over 32 group-maxes (16 bmax each): >=32 bmax values >= T, so
// T <= 16th-largest bmax <= v16 -> provably safe; survivors stay small.
__global__ void __launch_bounds__(256) k5s() {
    __shared__ float sT;
    int b = blockIdx.y, ch = blockIdx.x;
    int tid = threadIdx.x, lane = tid & 31;

    if (tid < 32) {
        float mx = -1e30f;
        #pragma unroll
        for (int j = 0; j < NBLK / 32; ++j)
            mx = fmaxf(mx, g_bmax[b * NBLK + lane * (NBLK / 32) + j]);
        #pragma unroll
        for (int off = 16; off; off >>= 1)
            mx = fminf(mx, __shfl_xor_sync(0xffffffffu, mx, off));
        if (lane == 0) sT = mx;
    }
    __syncthreads();

    float T = sT;
    const float4* rowv = (const float4*)(g_sim + (size_t)b * SS + (size_t)ch * CHSZ);
    int base = ch * CHSZ;
    #pragma unroll
    for (int it = 0; it < 8; ++it) {
        float4 v = rowv[it * 256 + tid];
        float vm = fmaxf(fmaxf(v.x, v.y), fmaxf(v.z, v.w));
        if (vm >= T) {
            float vals[4] = {v.x, v.y, v.z, v.w};
            int sb = base + (it * 256 + tid) * 4;
            #pragma unroll
            for (int j = 0; j < 4; ++j) {
                if (vals[j] >= T) {
                    int p = atomicAdd(&g_scnt[b], 1);
                    if (p < SCAP) {
                        g_surv_v[b * SCAP + p] = vals[j];
                        g_surv_i[b * SCAP + p] = sb + j;
                    }
                }
            }
        }
    }
}

// ---------------- K5b: final top-16 + softmax + proto gather ------------
__global__ void __launch_bounds__(128) k5b(const float* __restrict__ mem) {
    __shared__ float cv[SCAP];
    __shared__ int   ci[SCAP];
    __shared__ float selv[KTOP];
    __shared__ int   seli[KTOP];
    __shared__ float attn[KTOP];
    int b = blockIdx.x, tid = threadIdx.x, lane = tid & 31;
    int n = min(g_scnt[b], SCAP);

    for (int i = tid; i < n; i += 128) {
        cv[i] = g_surv_v[b * SCAP + i];
        ci[i] = g_surv_i[b * SCAP + i];
    }
    __syncthreads();

    if (tid < 32) {
        #pragma unroll 1
        for (int r = 0; r < KTOP; ++r) {
            float mv = -1e30f; int gi = 0x7fffffff; int mi = 0;
            for (int i = lane; i < n; i += 32) {
                float v = cv[i]; int idx = ci[i];
                if (v > mv || (v == mv && idx < gi)) { mv = v; gi = idx; mi = i; }
            }
            float bv = mv; int bgi = gi; int bmi = mi;
            #pragma unroll
            for (int off = 16; off; off >>= 1) {
                float ov  = __shfl_xor_sync(0xffffffffu, bv, off);
                int   ogi = __shfl_xor_sync(0xffffffffu, bgi, off);
                int   omi = __shfl_xor_sync(0xffffffffu, bmi, off);
                if (ov > bv || (ov == bv && ogi < bgi)) { bv = ov; bgi = ogi; bmi = omi; }
            }
            if (lane == 0) {
                selv[r] = bv; seli[r] = bgi;
                cv[bmi] = -1e30f;
            }
            __syncwarp();
        }
        if (lane == 0) {
            float mx = selv[0];
            float e[KTOP], ssum = 0.f;
            #pragma unroll
            for (int k = 0; k < KTOP; ++k) { e[k] = expf(selv[k] - mx); ssum += e[k]; }
            #pragma unroll
            for (int k = 0; k < KTOP; ++k) attn[k] = e[k] / ssum;
        }
    }
    __syncthreads();

    float acc = 0.f;
    #pragma unroll
    for (int k = 0; k < KTOP; ++k)
        acc = fmaf(attn[k], mem[(size_t)seli[k] * 128 + tid], acc);
    g_proto[b * 128 + tid] = acc;
}

// ---------------- K6: out = x + scale * proto ---------------------------
__global__ void __launch_bounds__(256) k6_add(const float* __restrict__ x,
                                              const float* __restrict__ scale_p,
                                              float* __restrict__ out) {
    __shared__ float pr[128];
    __shared__ float sc;
    int b = blockIdx.y;
    if (threadIdx.x < 128) pr[threadIdx.x] = g_proto[b * 128 + threadIdx.x];
    if (threadIdx.x == 0) sc = *scale_p;
    __syncthreads();

    float s = sc;
    const float4* xv = (const float4*)x;
    float4* ov = (float4*)out;
    size_t f0 = ((size_t)b * (NN * DD) + (size_t)blockIdx.x * 4096) >> 2;
    #pragma unroll
    for (int it = 0; it < 4; ++it) {
        size_t f = f0 + it * 256 + threadIdx.x;
        float4 v = xv[f];
        int d4 = (int)(f & 31);
        const float* p = &pr[d4 * 4];
        v.x = fmaf(s, p[0], v.x);
        v.y = fmaf(s, p[1], v.y);
        v.z = fmaf(s, p[2], v.z);
        v.w = fmaf(s, p[3], v.w);
        ov[f] = v;
    }
}

// ---------------- launch -------------------------------------------------
extern "C" void kernel_launch(void* const* d_in, const int* in_sizes, int n_in,
                              void* d_out, int out_size) {
    const float* x      = (const float*)d_in[0];
    const float* conv_w = (const float*)d_in[1];
    const float* conv_b = (const float*)d_in[2];
    const float* memory = (const float*)d_in[3];
    const float* scale  = (const float*)d_in[4];
    float* out = (float*)d_out;

    cudaFuncSetAttribute(k2_mma, cudaFuncAttributeMaxDynamicSharedMemorySize, K2_SMEM);
    cudaFuncSetAttribute(k4f, cudaFuncAttributeMaxDynamicSharedMemorySize, K4_SMEM);

    k2_mma<<<BB * 4, 128, K2_SMEM>>>(x, conv_w, conv_b);
    k3_q<<<BB, 128>>>();
    k4f<<<NBLK, 256, K4_SMEM>>>(memory);
    dim3 g5s(NCH, BB);
    k5s<<<g5s, 256>>>();
    k5b<<<BB, 128>>>(memory);
    dim3 g6(128, BB);
    k6_add<<<g6, 256>>>(x, scale, out);
    (void)in_sizes; (void)n_in; (void)out_size;
}

// round 13
// speedup vs baseline: 2.0404x; 1.2355x over previous
#include <cuda_runtime.h>
#include <cuda_fp16.h>
#include <math.h>
#include <stdint.h>

#define BB 64
#define NN 4096
#define DD 128
#define SS 65536
#define KTOP 16
#define NCH 8                         // filter chunks per b
#define CHSZ (SS / NCH)               // 8192 halves
#define NBLK 512                      // k4fh blocks (128 s each)
#define SCAP 2560                     // survivor capacity

typedef unsigned long long ull;

// ---------------- scratch (device globals; allocation-free) ----------------
__device__ float  g_qpart[BB * 4 * DD];   // per-CTA partial gelu sums
__device__ float  g_qn[BB * DD];          // normalized q: [b][d]
__device__ __half g_simh[(size_t)BB * SS];// cosine sims fp16          (8 MB)
__device__ float  g_proto[BB * DD];
__device__ float  g_bmax[BB * NBLK];      // per-(b, block) max
__device__ int    g_scnt[BB];             // per-b survivor count
__device__ float  g_surv_v[BB * SCAP];
__device__ int    g_surv_i[BB * SCAP];

// ---------------- generic helpers ----------------
// fast exact-enough gelu: erf via Abramowitz-Stegun 7.1.26 (|eps|<=1.5e-7)
__device__ __forceinline__ float gelu_exact(float z) {
    float x = z * 0.70710678118654752f;
    float ax = fabsf(x);
    float t = __fdividef(1.0f, fmaf(0.3275911f, ax, 1.0f));
    float p = t * fmaf(t, fmaf(t, fmaf(t, fmaf(t, 1.061405429f, -1.453152027f),
                                       1.421413741f), -0.284496736f), 0.254829592f);
    float e = __expf(-x * x);
    float er = copysignf(fmaf(-p, e, 1.0f), x);
    return 0.5f * z * (1.0f + er);
}
// pack two fp32 -> f16x2 (lo = first arg, hi = second)
__device__ __forceinline__ uint32_t hpack(float lo, float hi) {
    uint32_t r;
    asm("cvt.rn.f16x2.f32 %0, %1, %2;" : "=r"(r) : "f"(hi), "f"(lo));
    return r;
}

// fp16 m16n8k16 mma.sync
__device__ __forceinline__ void mma_f16(float* c, uint32_t a0, uint32_t a1,
                                        uint32_t a2, uint32_t a3,
                                        uint32_t b0, uint32_t b1) {
    asm volatile(
        "mma.sync.aligned.m16n8k16.row.col.f32.f16.f16.f32 "
        "{%0,%1,%2,%3}, {%4,%5,%6,%7}, {%8,%9}, {%0,%1,%2,%3};"
        : "+f"(c[0]), "+f"(c[1]), "+f"(c[2]), "+f"(c[3])
        : "r"(a0), "r"(a1), "r"(a2), "r"(a3), "r"(b0), "r"(b1));
}

// ---------------- K2: fp16 mma conv1d+GeLU+sum-over-n -------------------
// grid 256 = (b, quarter-n), 128 threads (4 warps = 4 e-quarters),
// tile 64n x 128e, 32 steps, 2-stage A ring, 2 CTAs/SM.
#define WS16 136                     // f16 per W row (128 + 8 pad)
#define AS16 72                      // f16 per A row (64 + 8 pad)
#define AB16 (64 * AS16)             // 4608 f16 per A buffer (9216 B)
#define O_W    0                     // 34816 B
#define O_A    34816                 // 2 * 9216 = 18432 B
#define O_BIAS 53248                 // 512 B
#define O_RED  53760                 // 512 B
#define K2_SMEM 54784

__global__ void __launch_bounds__(128, 2) k2_mma(const float* __restrict__ x,
                                                 const float* __restrict__ w,
                                                 const float* __restrict__ bias) {
    extern __shared__ char smc[];
    uint16_t* ws    = (uint16_t*)(smc + O_W);
    uint16_t* ab    = (uint16_t*)(smc + O_A);
    float*    sbias = (float*)(smc + O_BIAS);
    float*    red   = (float*)(smc + O_RED);

    int tid = threadIdx.x, wid = tid >> 5, lane = tid & 31;
    int g = lane >> 2, kc = lane & 3;
    int cta = blockIdx.x, b = cta >> 2, quarter = cta & 3;
    const float* xb = x + ((size_t)b * NN + (size_t)quarter * 1024) * DD;

    for (int i = tid; i < 4096; i += 128) {      // float4 over [128e][32]
        float4 v = ((const float4*)w)[i];
        int e = i >> 5, d0 = (i & 31) * 4;
        *(uint2*)&ws[e * WS16 + d0] = make_uint2(hpack(v.x, v.y), hpack(v.z, v.w));
    }
    sbias[tid] = bias[tid];

    int ew = wid * 32;

    float c[4][4][4];
    #pragma unroll
    for (int mf = 0; mf < 4; ++mf)
        #pragma unroll
        for (int ef = 0; ef < 4; ++ef)
            #pragma unroll
            for (int q = 0; q < 4; ++q) c[mf][ef][q] = 0.f;
    float es[8];
    #pragma unroll
    for (int s = 0; s < 8; ++s) es[s] = 0.f;

    float4 r8[8];
    auto ldg = [&](int gstep) {
        int t = gstep >> 1, h = gstep & 1;
        const float* base = xb + (size_t)t * (64 * DD) + h * 64;
        #pragma unroll
        for (int j = 0; j < 8; ++j) {
            int idx = j * 128 + tid;
            int row = idx >> 4, seg = idx & 15;
            r8[j] = *(const float4*)(base + (size_t)row * DD + seg * 4);
        }
    };
    auto sts = [&](int buf) {
        uint16_t* d = ab + buf * AB16;
        #pragma unroll
        for (int j = 0; j < 8; ++j) {
            int idx = j * 128 + tid;
            int row = idx >> 4, seg = idx & 15;
            *(uint2*)&d[row * AS16 + seg * 4] =
                make_uint2(hpack(r8[j].x, r8[j].y), hpack(r8[j].z, r8[j].w));
        }
    };

    ldg(0); sts(0);
    ldg(1);
    __syncthreads();

    float bs[8];
    #pragma unroll
    for (int ef = 0; ef < 4; ++ef) {
        bs[ef * 2 + 0] = sbias[ew + ef * 8 + 2 * kc + 0];
        bs[ef * 2 + 1] = sbias[ew + ef * 8 + 2 * kc + 1];
    }

    #pragma unroll 1
    for (int step = 0; step < 32; ++step) {
        if (step < 31) sts((step + 1) & 1);
        if (step < 30) ldg(step + 2);

        const uint16_t* A = ab + (step & 1) * AB16;
        int kg0 = (step & 1) * 64;
        #pragma unroll
        for (int ks = 0; ks < 4; ++ks) {
            int kb = ks * 16;
            uint32_t a[4][4];
            #pragma unroll
            for (int mf = 0; mf < 4; ++mf) {
                int r = g + mf * 16;
                a[mf][0] = *(const uint32_t*)&A[r * AS16 + kb + 2 * kc];
                a[mf][1] = *(const uint32_t*)&A[(r + 8) * AS16 + kb + 2 * kc];
                a[mf][2] = *(const uint32_t*)&A[r * AS16 + kb + 2 * kc + 8];
                a[mf][3] = *(const uint32_t*)&A[(r + 8) * AS16 + kb + 2 * kc + 8];
            }
            #pragma unroll
            for (int ef = 0; ef < 4; ++ef) {
                int e = ew + ef * 8 + g;
                uint32_t b0 = *(const uint32_t*)&ws[e * WS16 + kg0 + kb + 2 * kc];
                uint32_t b1 = *(const uint32_t*)&ws[e * WS16 + kg0 + kb + 2 * kc + 8];
                #pragma unroll
                for (int mf = 0; mf < 4; ++mf)
                    mma_f16(c[mf][ef], a[mf][0], a[mf][1], a[mf][2], a[mf][3], b0, b1);
            }
        }

        if ((step & 1) == 1) {
            #pragma unroll
            for (int mf = 0; mf < 4; ++mf)
                #pragma unroll
                for (int ef = 0; ef < 4; ++ef)
                    #pragma unroll
                    for (int q = 0; q < 4; ++q) {
                        int s = ef * 2 + (q & 1);
                        es[s] += gelu_exact(c[mf][ef][q] + bs[s]);
                        c[mf][ef][q] = 0.f;
                    }
        }
        __syncthreads();
    }

    #pragma unroll
    for (int off = 16; off >= 4; off >>= 1)
        #pragma unroll
        for (int s = 0; s < 8; ++s)
            es[s] += __shfl_xor_sync(0xffffffffu, es[s], off);
    if (g == 0) {
        #pragma unroll
        for (int s = 0; s < 8; ++s) {
            int ecol = ew + (s >> 1) * 8 + 2 * kc + (s & 1);
            red[ecol] = es[s];
        }
    }
    __syncthreads();
    g_qpart[(b * 4 + quarter) * 128 + tid] = red[tid];
}

// ---------------- K3: finalize q + normalize ([b][d] layout) ------------
__global__ void k3_q() {
    int b = blockIdx.x, e = threadIdx.x;
    float q = g_qpart[b * 512 + e] + g_qpart[b * 512 + 128 + e] +
              g_qpart[b * 512 + 256 + e] + g_qpart[b * 512 + 384 + e];
    __shared__ float sr[128];
    sr[e] = q * q;
    __syncthreads();
    for (int off = 64; off; off >>= 1) {
        if (e < off) sr[e] += sr[e + off];
        __syncthreads();
    }
    float inv = 1.0f / fmaxf(sqrtf(sr[0]), 1e-12f);
    g_qn[b * 128 + e] = q * inv;
}

// ---------------- K4fh: fp16 MMA sim GEMM (fused normalize) -------------
// Block = 128 s x 64 b. mn stays [s][k] (memory's native layout, no
// transpose); qn [b][k]. 8 warps own 16-s slices. Reuses K2's fragment map.
#define QS16 136                     // f16 per row (128 + 8 pad)
#define H_QN   0                     // 64*136*2  = 17408 B
#define H_MN   17408                 // 128*136*2 = 34816 B
#define H_WMAX 52224                 // 8*64*4    = 2048 B
#define K4_SMEM 54400

__global__ void __launch_bounds__(256, 2) k4fh(const float* __restrict__ mem) {
    extern __shared__ char sm4[];
    uint16_t* qn_h = (uint16_t*)(sm4 + H_QN);
    uint16_t* mn_h = (uint16_t*)(sm4 + H_MN);
    float*    wmax = (float*)(sm4 + H_WMAX);
    int tid = threadIdx.x, wid = tid >> 5, lane = tid & 31;
    int g = lane >> 2, kc = lane & 3;
    int s0 = blockIdx.x * 128;

    if (blockIdx.x == 0 && tid < BB) g_scnt[tid] = 0;   // reset for k5s

    // ---- stage qn as fp16 [b][k] ----
    #pragma unroll
    for (int j = 0; j < 8; ++j) {
        int idx = j * 256 + tid;                 // float4 over [64][128]
        int brow = idx >> 5, seg = idx & 31;
        float4 v = ((const float4*)g_qn)[idx];
        *(uint2*)&qn_h[brow * QS16 + seg * 4] =
            make_uint2(hpack(v.x, v.y), hpack(v.z, v.w));
    }

    // ---- normalize memory rows -> fp16 [s][k] (native layout) ----
    {
        int row = tid >> 1, h = tid & 1;
        const float4* src = (const float4*)(mem + (size_t)(s0 + row) * 128 + h * 64);
        float acc = 0.f;
        #pragma unroll
        for (int i = 0; i < 16; ++i) {
            float4 v = src[i];
            acc = fmaf(v.x, v.x, acc); acc = fmaf(v.y, v.y, acc);
            acc = fmaf(v.z, v.z, acc); acc = fmaf(v.w, v.w, acc);
        }
        acc += __shfl_xor_sync(0xffffffffu, acc, 1);
        float inv = 1.0f / fmaxf(sqrtf(acc), 1e-12f);
        uint16_t* dst = mn_h + row * QS16 + h * 64;
        #pragma unroll
        for (int i = 0; i < 16; ++i) {
            float4 v = src[i];                   // L1 hit (just read)
            *(uint2*)(dst + i * 4) =
                make_uint2(hpack(v.x * inv, v.y * inv), hpack(v.z * inv, v.w * inv));
        }
    }
    __syncthreads();

    // ---- GEMM: D[64b][16s-slice] per warp, k=128 ----
    int sw = wid * 16;
    float c[4][2][4];
    #pragma unroll
    for (int mf = 0; mf < 4; ++mf)
        #pragma unroll
        for (int ef = 0; ef < 2; ++ef)
            #pragma unroll
            for (int q = 0; q < 4; ++q) c[mf][ef][q] = 0.f;

    #pragma unroll
    for (int ks = 0; ks < 8; ++ks) {
        int kb = ks * 16;
        uint32_t a[4][4];
        #pragma unroll
        for (int mf = 0; mf < 4; ++mf) {
            int r = g + mf * 16;
            a[mf][0] = *(const uint32_t*)&qn_h[r * QS16 + kb + 2 * kc];
            a[mf][1] = *(const uint32_t*)&qn_h[(r + 8) * QS16 + kb + 2 * kc];
            a[mf][2] = *(const uint32_t*)&qn_h[r * QS16 + kb + 2 * kc + 8];
            a[mf][3] = *(const uint32_t*)&qn_h[(r + 8) * QS16 + kb + 2 * kc + 8];
        }
        #pragma unroll
        for (int ef = 0; ef < 2; ++ef) {
            int n = sw + ef * 8 + g;
            uint32_t b0 = *(const uint32_t*)&mn_h[n * QS16 + kb + 2 * kc];
            uint32_t b1 = *(const uint32_t*)&mn_h[n * QS16 + kb + 2 * kc + 8];
            #pragma unroll
            for (int mf = 0; mf < 4; ++mf)
                mma_f16(c[mf][ef], a[mf][0], a[mf][1], a[mf][2], a[mf][3], b0, b1);
        }
    }

    // ---- epilogue: store fp16 sims + per-b row maxes ----
    #pragma unroll
    for (int mf = 0; mf < 4; ++mf) {
        #pragma unroll
        for (int h = 0; h < 2; ++h) {
            int row = mf * 16 + 8 * h + g;       // b index
            float rm = -1e30f;
            #pragma unroll
            for (int ef = 0; ef < 2; ++ef) {
                float lo = c[mf][ef][2 * h], hi = c[mf][ef][2 * h + 1];
                *(uint32_t*)&g_simh[(size_t)row * SS + s0 + sw + ef * 8 + 2 * kc] =
                    hpack(lo, hi);
                rm = fmaxf(rm, fmaxf(lo, hi));
            }
            rm = fmaxf(rm, __shfl_xor_sync(0xffffffffu, rm, 1));
            rm = fmaxf(rm, __shfl_xor_sync(0xffffffffu, rm, 2));
            if (kc == 0) wmax[wid * 64 + row] = rm;
        }
    }
    __syncthreads();
    if (tid < 64) {
        float m = wmax[tid];
        #pragma unroll
        for (int w = 1; w < 8; ++w) m = fmaxf(m, wmax[w * 64 + tid]);
        g_bmax[tid * NBLK + blockIdx.x] = m;
    }
}

// ---------------- K5s: inline threshold + fp16 stream filter ------------
// T = min over 32 group-maxes (16 bmax each): provably <= v16.
__global__ void __launch_bounds__(256) k5s() {
    __shared__ float sT;
    int b = blockIdx.y, ch = blockIdx.x;
    int tid = threadIdx.x, lane = tid & 31;

    if (tid < 32) {
        float mx = -1e30f;
        #pragma unroll
        for (int j = 0; j < NBLK / 32; ++j)
            mx = fmaxf(mx, g_bmax[b * NBLK + lane * (NBLK / 32) + j]);
        #pragma unroll
        for (int off = 16; off; off >>= 1)
            mx = fminf(mx, __shfl_xor_sync(0xffffffffu, mx, off));
        if (lane == 0) sT = mx;
    }
    __syncthreads();

    float T = sT;
    const uint4* rowv = (const uint4*)(g_simh + (size_t)b * SS + (size_t)ch * CHSZ);
    int base = ch * CHSZ;
    #pragma unroll
    for (int it = 0; it < 4; ++it) {
        uint4 u = rowv[it * 256 + tid];          // 8 halves
        float2 f0 = __half22float2(*(__half2*)&u.x);
        float2 f1 = __half22float2(*(__half2*)&u.y);
        float2 f2 = __half22float2(*(__half2*)&u.z);
        float2 f3 = __half22float2(*(__half2*)&u.w);
        float vm = fmaxf(fmaxf(fmaxf(f0.x, f0.y), fmaxf(f1.x, f1.y)),
                         fmaxf(fmaxf(f2.x, f2.y), fmaxf(f3.x, f3.y)));
        if (vm >= T) {
            float vals[8] = {f0.x, f0.y, f1.x, f1.y, f2.x, f2.y, f3.x, f3.y};
            int sb = base + (it * 256 + tid) * 8;
            #pragma unroll
            for (int j = 0; j < 8; ++j) {
                if (vals[j] >= T) {
                    int p = atomicAdd(&g_scnt[b], 1);
                    if (p < SCAP) {
                        g_surv_v[b * SCAP + p] = vals[j];
                        g_surv_i[b * SCAP + p] = sb + j;
                    }
                }
            }
        }
    }
}

// ---------------- K5b: final top-16 + softmax + proto gather ------------
__global__ void __launch_bounds__(128) k5b(const float* __restrict__ mem) {
    __shared__ float cv[SCAP];
    __shared__ int   ci[SCAP];
    __shared__ float selv[KTOP];
    __shared__ int   seli[KTOP];
    __shared__ float attn[KTOP];
    int b = blockIdx.x, tid = threadIdx.x, lane = tid & 31;
    int n = min(g_scnt[b], SCAP);

    for (int i = tid; i < n; i += 128) {
        cv[i] = g_surv_v[b * SCAP + i];
        ci[i] = g_surv_i[b * SCAP + i];
    }
    __syncthreads();

    if (tid < 32) {
        #pragma unroll 1
        for (int r = 0; r < KTOP; ++r) {
            float mv = -1e30f; int gi = 0x7fffffff; int mi = 0;
            for (int i = lane; i < n; i += 32) {
                float v = cv[i]; int idx = ci[i];
                if (v > mv || (v == mv && idx < gi)) { mv = v; gi = idx; mi = i; }
            }
            float bv = mv; int bgi = gi; int bmi = mi;
            #pragma unroll
            for (int off = 16; off; off >>= 1) {
                float ov  = __shfl_xor_sync(0xffffffffu, bv, off);
                int   ogi = __shfl_xor_sync(0xffffffffu, bgi, off);
                int   omi = __shfl_xor_sync(0xffffffffu, bmi, off);
                if (ov > bv || (ov == bv && ogi < bgi)) { bv = ov; bgi = ogi; bmi = omi; }
            }
            if (lane == 0) {
                selv[r] = bv; seli[r] = bgi;
                cv[bmi] = -1e30f;
            }
            __syncwarp();
        }
        if (lane == 0) {
            float mx = selv[0];
            float e[KTOP], ssum = 0.f;
            #pragma unroll
            for (int k = 0; k < KTOP; ++k) { e[k] = expf(selv[k] - mx); ssum += e[k]; }
            #pragma unroll
            for (int k = 0; k < KTOP; ++k) attn[k] = e[k] / ssum;
        }
    }
    __syncthreads();

    float acc = 0.f;
    #pragma unroll
    for (int k = 0; k < KTOP; ++k)
        acc = fmaf(attn[k], mem[(size_t)seli[k] * 128 + tid], acc);
    g_proto[b * 128 + tid] = acc;
}

// ---------------- K6: out = x + scale * proto ---------------------------
__global__ void __launch_bounds__(256) k6_add(const float* __restrict__ x,
                                              const float* __restrict__ scale_p,
                                              float* __restrict__ out) {
    __shared__ float pr[128];
    __shared__ float sc;
    int b = blockIdx.y;
    if (threadIdx.x < 128) pr[threadIdx.x] = g_proto[b * 128 + threadIdx.x];
    if (threadIdx.x == 0) sc = *scale_p;
    __syncthreads();

    float s = sc;
    const float4* xv = (const float4*)x;
    float4* ov = (float4*)out;
    size_t f0 = ((size_t)b * (NN * DD) + (size_t)blockIdx.x * 4096) >> 2;
    #pragma unroll
    for (int it = 0; it < 4; ++it) {
        size_t f = f0 + it * 256 + threadIdx.x;
        float4 v = xv[f];
        int d4 = (int)(f & 31);
        const float* p = &pr[d4 * 4];
        v.x = fmaf(s, p[0], v.x);
        v.y = fmaf(s, p[1], v.y);
        v.z = fmaf(s, p[2], v.z);
        v.w = fmaf(s, p[3], v.w);
        ov[f] = v;
    }
}

// ---------------- launch -------------------------------------------------
extern "C" void kernel_launch(void* const* d_in, const int* in_sizes, int n_in,
                              void* d_out, int out_size) {
    const float* x      = (const float*)d_in[0];
    const float* conv_w = (const float*)d_in[1];
    const float* conv_b = (const float*)d_in[2];
    const float* memory = (const float*)d_in[3];
    const float* scale  = (const float*)d_in[4];
    float* out = (float*)d_out;

    cudaFuncSetAttribute(k2_mma, cudaFuncAttributeMaxDynamicSharedMemorySize, K2_SMEM);
    cudaFuncSetAttribute(k4fh, cudaFuncAttributeMaxDynamicSharedMemorySize, K4_SMEM);

    k2_mma<<<BB * 4, 128, K2_SMEM>>>(x, conv_w, conv_b);
    k3_q<<<BB, 128>>>();
    k4fh<<<NBLK, 256, K4_SMEM>>>(memory);
    dim3 g5s(NCH, BB);
    k5s<<<g5s, 256>>>();
    k5b<<<BB, 128>>>(memory);
    dim3 g6(128, BB);
    k6_add<<<g6, 256>>>(x, scale, out);
    (void)in_sizes; (void)n_in; (void)out_size;
}